// round 10
// baseline (speedup 1.0000x reference)
#include <cuda_runtime.h>
#include <math.h>

#define N_NODES 100000
#define E_MAX   1600000
#define SCAN_BLOCKS ((N_NODES + 255) / 256)   // 391

// ---------------- scratch (static __device__, no allocation) ----------------
__device__ int    g_deg[2 * N_NODES];   // [0..N): deg_out, [N..2N): deg_in (single memset)
__device__ float  g_rs_out[N_NODES];
__device__ float  g_rs_in[N_NODES];
__device__ float4 g_y[N_NODES * 16];    // layer-1 GEMM output (gather-1 input)
__device__ float4 g_y2[N_NODES * 16];   // fused kernel output (final-gather input)
__device__ int    g_row_ptr[N_NODES];   // CSR row starts (by dst)
__device__ int    g_cursor[N_NODES];    // fill cursors
__device__ int    g_col[E_MAX];         // CSR column indices (= src node)
__device__ int    g_partials[SCAN_BLOCKS];

// ---------------- degrees ----------------
__global__ void degree_kernel(const int* __restrict__ src, const int* __restrict__ dst, int E) {
    int e = blockIdx.x * blockDim.x + threadIdx.x;
    if (e < E) {
        atomicAdd(&g_deg[src[e]], 1);             // deg_out
        atomicAdd(&g_deg[N_NODES + dst[e]], 1);   // deg_in
    }
}

// ---------------- CSR build: 2-level exclusive scan of deg_in + fill ----------------
__global__ void scan_blocks_kernel() {
    __shared__ int sh[256];
    int t = threadIdx.x;
    int i = blockIdx.x * 256 + t;
    int v = (i < N_NODES) ? g_deg[N_NODES + i] : 0;
    sh[t] = v;
    __syncthreads();
#pragma unroll
    for (int off = 1; off < 256; off <<= 1) {
        int cur = sh[t];
        int add = (t >= off) ? sh[t - off] : 0;
        __syncthreads();
        sh[t] = cur + add;
        __syncthreads();
    }
    if (i < N_NODES) g_row_ptr[i] = sh[t] - v;      // block-local exclusive
    if (t == 255) g_partials[blockIdx.x] = sh[255]; // block total
}

__global__ void scan_partials_kernel() {
    __shared__ int sh[512];
    int t = threadIdx.x;
    int v = (t < SCAN_BLOCKS) ? g_partials[t] : 0;
    sh[t] = v;
    __syncthreads();
#pragma unroll
    for (int off = 1; off < 512; off <<= 1) {
        int cur = sh[t];
        int add = (t >= off) ? sh[t - off] : 0;
        __syncthreads();
        sh[t] = cur + add;
        __syncthreads();
    }
    if (t < SCAN_BLOCKS) g_partials[t] = sh[t] - v; // exclusive block offsets
}

// scan finalize + rsqrt norms (fused)
__global__ void scan_add_kernel() {
    int i = blockIdx.x * blockDim.x + threadIdx.x;
    if (i < N_NODES) {
        int r = g_row_ptr[i] + g_partials[i >> 8];
        g_row_ptr[i] = r;
        g_cursor[i]  = r;
        g_rs_out[i] = rsqrtf((float)max(g_deg[i], 1));
        g_rs_in[i]  = rsqrtf((float)max(g_deg[N_NODES + i], 1));
    }
}

__global__ void csr_fill_kernel(const int* __restrict__ src, const int* __restrict__ dst, int E) {
    int e = blockIdx.x * blockDim.x + threadIdx.x;
    if (e < E) {
        int d = dst[e];
        int pos = atomicAdd(&g_cursor[d], 1);
        g_col[pos] = src[e];
    }
}

// ---------------- GEMM1: g_y[n,64] = (x[n,:] * rs_out[n]) @ W1   (K=128) ----------------
__global__ __launch_bounds__(128) void gemm_kernel(
    const float* __restrict__ X, const float* __restrict__ W)
{
    constexpr int K = 128;
    extern __shared__ float smem[];
    float* Ws = smem;                    // K*64 floats
    float* xs = smem + K * 64;           // 128*(K+1) floats (padded rows)
    const int tid = threadIdx.x;
    const int node0 = blockIdx.x * 128;

    for (int i = tid; i < K * 16; i += 128)
        ((float4*)Ws)[i] = ((const float4*)W)[i];

    constexpr int K4 = K / 4;
    for (int i = tid; i < 128 * K4; i += 128) {
        int r = i / K4;
        int c4 = i % K4;
        int node = node0 + r;
        float4 v = make_float4(0.f, 0.f, 0.f, 0.f);
        if (node < N_NODES) {
            v = ((const float4*)X)[(size_t)node * K4 + c4];
            float ro = g_rs_out[node];
            v.x *= ro; v.y *= ro; v.z *= ro; v.w *= ro;
        }
        float* xr = xs + r * (K + 1) + c4 * 4;
        xr[0] = v.x; xr[1] = v.y; xr[2] = v.z; xr[3] = v.w;
    }
    __syncthreads();

    float acc[64];
#pragma unroll
    for (int j = 0; j < 64; j++) acc[j] = 0.f;

    const float4* Ws4 = (const float4*)Ws;
    const float* xrow = xs + tid * (K + 1);
#pragma unroll 4
    for (int k = 0; k < K; k++) {
        float xv = xrow[k];
#pragma unroll
        for (int j4 = 0; j4 < 16; j4++) {
            float4 w = Ws4[k * 16 + j4];
            acc[j4 * 4 + 0] = fmaf(xv, w.x, acc[j4 * 4 + 0]);
            acc[j4 * 4 + 1] = fmaf(xv, w.y, acc[j4 * 4 + 1]);
            acc[j4 * 4 + 2] = fmaf(xv, w.z, acc[j4 * 4 + 2]);
            acc[j4 * 4 + 3] = fmaf(xv, w.w, acc[j4 * 4 + 3]);
        }
    }

    int node = node0 + tid;
    if (node < N_NODES) {
        float4* out4 = &g_y[(size_t)node * 16];
#pragma unroll
        for (int j4 = 0; j4 < 16; j4++)
            out4[j4] = make_float4(acc[j4 * 4 + 0], acc[j4 * 4 + 1],
                                   acc[j4 * 4 + 2], acc[j4 * 4 + 3]);
    }
}

// ---------------- 4-way unrolled CSR gather sum (helper) ----------------
__device__ __forceinline__ float4 gather_sum(const float4* __restrict__ ybuf,
                                             int start, int deg, int part)
{
    float4 a0 = make_float4(0.f, 0.f, 0.f, 0.f);
    float4 a1 = make_float4(0.f, 0.f, 0.f, 0.f);
    float4 a2 = make_float4(0.f, 0.f, 0.f, 0.f);
    float4 a3 = make_float4(0.f, 0.f, 0.f, 0.f);
    const int end = start + deg;
    int e = start;
    for (; e + 3 < end; e += 4) {
        int s0 = __ldg(&g_col[e]);
        int s1 = __ldg(&g_col[e + 1]);
        int s2 = __ldg(&g_col[e + 2]);
        int s3 = __ldg(&g_col[e + 3]);
        float4 v0 = ybuf[(size_t)s0 * 16 + part];
        float4 v1 = ybuf[(size_t)s1 * 16 + part];
        float4 v2 = ybuf[(size_t)s2 * 16 + part];
        float4 v3 = ybuf[(size_t)s3 * 16 + part];
        a0.x += v0.x; a0.y += v0.y; a0.z += v0.z; a0.w += v0.w;
        a1.x += v1.x; a1.y += v1.y; a1.z += v1.z; a1.w += v1.w;
        a2.x += v2.x; a2.y += v2.y; a2.z += v2.z; a2.w += v2.w;
        a3.x += v3.x; a3.y += v3.y; a3.z += v3.z; a3.w += v3.w;
    }
    for (; e < end; e++) {
        int s0 = __ldg(&g_col[e]);
        float4 v0 = ybuf[(size_t)s0 * 16 + part];
        a0.x += v0.x; a0.y += v0.y; a0.z += v0.z; a0.w += v0.w;
    }
    a0.x += a1.x + a2.x + a3.x;
    a0.y += a1.y + a2.y + a3.y;
    a0.z += a1.z + a2.z + a3.z;
    a0.w += a1.w + a2.w + a3.w;
    return a0;
}

// ---------------- fused: gather-1 + layer-2 transform + W2 matvec ----------------
// 8 nodes per 128-thread block; 16 threads per node.
//   agg = sum_{e: dst=n} g_y[src]                 (CSR gather)
//   h   = relu(agg * rs_in + b1) * rs_out          (node-local)
//   g_y2[n] = h @ W2                               (64x64 matvec from smem)
#define HSTR 68   // h row stride in floats (68 mod 32 = 4 -> conflict-free across 8 nodes)
__global__ __launch_bounds__(128) void gather_gemm2_kernel(
    const float* __restrict__ W2, const float* __restrict__ b1)
{
    __shared__ float W2s[64 * 64];
    __shared__ float hs[8 * HSTR];

    const int tid  = threadIdx.x;
    const int ln   = tid >> 4;            // local node 0..7
    const int part = tid & 15;
    const int node = blockIdx.x * 8 + ln;

    // stage W2 (row-major [64][64])
    for (int i = tid; i < 64 * 16; i += 128)
        ((float4*)W2s)[i] = ((const float4*)W2)[i];

    float4 h = make_float4(0.f, 0.f, 0.f, 0.f);
    if (node < N_NODES) {
        const int start = g_row_ptr[node];
        const int deg   = g_deg[N_NODES + node];
        float4 acc = gather_sum(g_y, start, deg, part);
        float ri = g_rs_in[node];
        float ro = g_rs_out[node];
        float4 bb = ((const float4*)b1)[part];
        h.x = fmaxf(fmaf(acc.x, ri, bb.x), 0.f) * ro;
        h.y = fmaxf(fmaf(acc.y, ri, bb.y), 0.f) * ro;
        h.z = fmaxf(fmaf(acc.z, ri, bb.z), 0.f) * ro;
        h.w = fmaxf(fmaf(acc.w, ri, bb.w), 0.f) * ro;
    }
    float* hr = hs + ln * HSTR + part * 4;
    hr[0] = h.x; hr[1] = h.y; hr[2] = h.z; hr[3] = h.w;
    __syncthreads();

    // matvec: y[j] = sum_k h[k] * W2[k][j], thread covers j = part*4..part*4+3
    float4 acc = make_float4(0.f, 0.f, 0.f, 0.f);
    const float* hrow = hs + ln * HSTR;
    const float4* W2s4 = (const float4*)W2s;
#pragma unroll 8
    for (int k = 0; k < 64; k++) {
        float hv = hrow[k];                    // broadcast within node group
        float4 w = W2s4[k * 16 + part];
        acc.x = fmaf(hv, w.x, acc.x);
        acc.y = fmaf(hv, w.y, acc.y);
        acc.z = fmaf(hv, w.z, acc.z);
        acc.w = fmaf(hv, w.w, acc.w);
    }
    if (node < N_NODES)
        g_y2[(size_t)node * 16 + part] = acc;
}

// ---------------- final gather: out[n] = (sum g_y2[src]) * rs_in + b2 ----------------
__global__ __launch_bounds__(128) void gather_final_kernel(float4* __restrict__ outp,
                                                           const float* __restrict__ b2)
{
    const int tid  = threadIdx.x;
    const int node = blockIdx.x * 8 + (tid >> 4);
    const int part = tid & 15;
    if (node >= N_NODES) return;

    const int start = g_row_ptr[node];
    const int deg   = g_deg[N_NODES + node];
    float4 acc = gather_sum(g_y2, start, deg, part);

    float ri = g_rs_in[node];
    float4 bb = ((const float4*)b2)[part];
    acc.x = fmaf(acc.x, ri, bb.x);
    acc.y = fmaf(acc.y, ri, bb.y);
    acc.z = fmaf(acc.z, ri, bb.z);
    acc.w = fmaf(acc.w, ri, bb.w);
    outp[(size_t)node * 16 + part] = acc;
}

// ---------------- launch ----------------
extern "C" void kernel_launch(void* const* d_in, const int* in_sizes, int n_in,
                              void* d_out, int out_size)
{
    // Positional defaults (setup_inputs dict order)
    const float* x   = (const float*)d_in[0];
    const int*   src = (const int*)d_in[1];
    const int*   dst = (const int*)d_in[2];
    const float* W1  = (const float*)d_in[3];
    const float* b1  = (const float*)d_in[4];
    const float* W2  = (const float*)d_in[5];
    const float* b2  = (const float*)d_in[6];
    int E = in_sizes[1];

    // Size-based identification (robust to metadata reordering)
    {
        int e_seen = 0, b_seen = 0;
        for (int i = 0; i < n_in; i++) {
            int s = in_sizes[i];
            if      (s == N_NODES * 128) x  = (const float*)d_in[i];
            else if (s == 128 * 64)      W1 = (const float*)d_in[i];
            else if (s == 64 * 64)       W2 = (const float*)d_in[i];
            else if (s == 64) { if (b_seen++ == 0) b1 = (const float*)d_in[i];
                                else               b2 = (const float*)d_in[i]; }
            else if (s > 64 * 64 && s != N_NODES * 128) {
                if (e_seen++ == 0) { src = (const int*)d_in[i]; E = s; }
                else                 dst = (const int*)d_in[i];
            }
        }
    }
    float* out = (float*)d_out;

    const int smem1 = (128 * 64 + 128 * 129) * (int)sizeof(float);  // 98816 B
    cudaFuncSetAttribute(gemm_kernel,
                         cudaFuncAttributeMaxDynamicSharedMemorySize, smem1);

    const int NB_N      = (N_NODES + 255) / 256;
    const int NB_E      = (E + 255) / 256;
    const int NB_GEMM   = (N_NODES + 127) / 128;
    const int NB_GATHER = (N_NODES + 7) / 8;

    // zero degrees via memset node (not a kernel launch -> keeps ncu -s 5 on gemm1)
    void* deg_ptr = nullptr;
    cudaGetSymbolAddress(&deg_ptr, g_deg);
    cudaMemsetAsync(deg_ptr, 0, 2 * N_NODES * sizeof(int), 0);

    // degrees + CSR build (dst-major) + norms
    degree_kernel<<<NB_E, 256>>>(src, dst, E);            // launch 1
    scan_blocks_kernel<<<SCAN_BLOCKS, 256>>>();           // launch 2
    scan_partials_kernel<<<1, 512>>>();                   // launch 3
    scan_add_kernel<<<NB_N, 256>>>();                     // launch 4 (+rsqrt)
    csr_fill_kernel<<<NB_E, 256>>>(src, dst, E);          // launch 5

    // layer 1 GEMM                                        // launch 6 <- ncu -s 5 target
    gemm_kernel<<<NB_GEMM, 128, smem1>>>(x, W1);

    // fused gather-1 + relu/norm + W2 matvec              // launch 7
    gather_gemm2_kernel<<<NB_GATHER, 128>>>(W2, b1);

    // final gather + rs_in + b2                           // launch 8
    gather_final_kernel<<<NB_GATHER, 128>>>((float4*)out, b2);
}

// round 13
// speedup vs baseline: 1.0537x; 1.0537x over previous
#include <cuda_runtime.h>
#include <cuda_fp16.h>
#include <math.h>

#define N_NODES 100000
#define E_MAX   1600000
#define SCAN_BLOCKS ((N_NODES + 255) / 256)   // 391

// ---------------- scratch (static __device__, no allocation) ----------------
__device__ int    g_deg[2 * N_NODES];   // [0..N): deg_out, [N..2N): deg_in (single memset)
__device__ float  g_rs_out[N_NODES];
__device__ float  g_rs_in[N_NODES];
__device__ __half g_yh[N_NODES * 64];   // layer-1 GEMM output, fp16 (gather-1 input)
__device__ __half g_y2h[N_NODES * 64];  // fused kernel output, fp16 (final-gather input)
__device__ int    g_row_ptr[N_NODES];   // CSR row starts (by dst)
__device__ int    g_cursor[N_NODES];    // fill cursors
__device__ int    g_col[E_MAX];         // CSR column indices (= src node)
__device__ int    g_partials[SCAN_BLOCKS];

// ---------------- degrees ----------------
__global__ void degree_kernel(const int* __restrict__ src, const int* __restrict__ dst, int E) {
    int e = blockIdx.x * blockDim.x + threadIdx.x;
    if (e < E) {
        atomicAdd(&g_deg[src[e]], 1);             // deg_out
        atomicAdd(&g_deg[N_NODES + dst[e]], 1);   // deg_in
    }
}

// ---------------- CSR build ----------------
__global__ void scan_blocks_kernel() {
    __shared__ int sh[256];
    int t = threadIdx.x;
    int i = blockIdx.x * 256 + t;
    int v = (i < N_NODES) ? g_deg[N_NODES + i] : 0;
    sh[t] = v;
    __syncthreads();
#pragma unroll
    for (int off = 1; off < 256; off <<= 1) {
        int cur = sh[t];
        int add = (t >= off) ? sh[t - off] : 0;
        __syncthreads();
        sh[t] = cur + add;
        __syncthreads();
    }
    if (i < N_NODES) g_row_ptr[i] = sh[t] - v;      // block-local exclusive
    if (t == 255) g_partials[blockIdx.x] = sh[255]; // block total
}

// fused: partials-prefix (each block reduces partials[0..blk)) + finalize + rsqrt
__global__ void scan_add_kernel() {
    __shared__ int ssum[256];
    const int t = threadIdx.x;
    const int blk = blockIdx.x;
    int s = 0;
    for (int j = t; j < blk; j += 256) s += g_partials[j];   // <=2 iters (391 partials)
    ssum[t] = s;
    __syncthreads();
#pragma unroll
    for (int off = 128; off; off >>= 1) {
        if (t < off) ssum[t] += ssum[t + off];
        __syncthreads();
    }
    const int base = ssum[0];
    const int i = blk * 256 + t;
    if (i < N_NODES) {
        int r = g_row_ptr[i] + base;
        g_row_ptr[i] = r;
        g_cursor[i]  = r;
        g_rs_out[i] = rsqrtf((float)max(g_deg[i], 1));
        g_rs_in[i]  = rsqrtf((float)max(g_deg[N_NODES + i], 1));
    }
}

__global__ void csr_fill_kernel(const int* __restrict__ src, const int* __restrict__ dst, int E) {
    int e = blockIdx.x * blockDim.x + threadIdx.x;
    if (e < E) {
        int d = dst[e];
        int pos = atomicAdd(&g_cursor[d], 1);
        g_col[pos] = src[e];
    }
}

// ---------------- GEMM1: g_yh[n,64] = fp16((x[n,:] * rs_out[n]) @ W1)  (K=128) --------
// Register-blocked: 128 threads, tile 128 nodes x 64 cols.
// Thread (tq = tid>>2, tc4 = tid&3) computes nodes {tq, tq+32, tq+64, tq+96}
// x cols {tc4*16 .. +15}.  Per k: 4 scalar LDS (bank-conflict-free, node stride 32
// x row-stride 129 => 32 distinct banks) + 4 LDS.128 of W + 64 FFMA -> FMA-bound.
__global__ __launch_bounds__(128) void gemm_kernel(
    const float* __restrict__ X, const float* __restrict__ W)
{
    constexpr int K = 128;
    extern __shared__ float smem[];
    float* Ws = smem;                    // K*64 floats
    float* xs = smem + K * 64;           // 128*(K+1) floats (padded rows)
    const int tid = threadIdx.x;
    const int node0 = blockIdx.x * 128;

    for (int i = tid; i < K * 16; i += 128)
        ((float4*)Ws)[i] = ((const float4*)W)[i];

    constexpr int K4 = K / 4;
    for (int i = tid; i < 128 * K4; i += 128) {
        int r = i / K4;
        int c4 = i % K4;
        int node = node0 + r;
        float4 v = make_float4(0.f, 0.f, 0.f, 0.f);
        if (node < N_NODES) {
            v = ((const float4*)X)[(size_t)node * K4 + c4];
            float ro = g_rs_out[node];
            v.x *= ro; v.y *= ro; v.z *= ro; v.w *= ro;
        }
        float* xr = xs + r * (K + 1) + c4 * 4;
        xr[0] = v.x; xr[1] = v.y; xr[2] = v.z; xr[3] = v.w;
    }
    __syncthreads();

    const int tq  = tid >> 2;          // node base 0..31
    const int tc4 = (tid & 3) * 4;     // W float4 index base (cols tc4*4 .. +15)

    float acc[4][16];
#pragma unroll
    for (int i = 0; i < 4; i++)
#pragma unroll
        for (int j = 0; j < 16; j++) acc[i][j] = 0.f;

    const float4* Ws4 = (const float4*)Ws;
#pragma unroll 4
    for (int k = 0; k < K; k++) {
        float xv[4];
#pragma unroll
        for (int i = 0; i < 4; i++)
            xv[i] = xs[(tq + 32 * i) * (K + 1) + k];
        float4 w[4];
#pragma unroll
        for (int j = 0; j < 4; j++)
            w[j] = Ws4[k * 16 + tc4 + j];
#pragma unroll
        for (int i = 0; i < 4; i++) {
#pragma unroll
            for (int j = 0; j < 4; j++) {
                acc[i][j * 4 + 0] = fmaf(xv[i], w[j].x, acc[i][j * 4 + 0]);
                acc[i][j * 4 + 1] = fmaf(xv[i], w[j].y, acc[i][j * 4 + 1]);
                acc[i][j * 4 + 2] = fmaf(xv[i], w[j].z, acc[i][j * 4 + 2]);
                acc[i][j * 4 + 3] = fmaf(xv[i], w[j].w, acc[i][j * 4 + 3]);
            }
        }
    }

    // store fp16: 16 cols = 32B = 2 x uint4 per node
#pragma unroll
    for (int i = 0; i < 4; i++) {
        int node = node0 + tq + 32 * i;
        if (node < N_NODES) {
            __half2 hp[8];
#pragma unroll
            for (int j = 0; j < 8; j++)
                hp[j] = __float22half2_rn(make_float2(acc[i][j * 2], acc[i][j * 2 + 1]));
            uint4* dstp = (uint4*)(g_yh + (size_t)node * 64 + tc4 * 4);
            dstp[0] = *(uint4*)&hp[0];
            dstp[1] = *(uint4*)&hp[4];
        }
    }
}

// ---------------- 4-way unrolled CSR gather sum over fp16 rows ----------------
// part in 0..15 covers 4 cols; per edge loads uint2 (4 halves = 8B).
__device__ __forceinline__ float4 gather_sum_h(const __half* __restrict__ ybuf,
                                               int start, int deg, int part)
{
    float4 a0 = make_float4(0.f, 0.f, 0.f, 0.f);
    float4 a1 = make_float4(0.f, 0.f, 0.f, 0.f);
    float4 a2 = make_float4(0.f, 0.f, 0.f, 0.f);
    float4 a3 = make_float4(0.f, 0.f, 0.f, 0.f);
    const int end = start + deg;
    int e = start;
    for (; e + 3 < end; e += 4) {
        int s0 = __ldg(&g_col[e]);
        int s1 = __ldg(&g_col[e + 1]);
        int s2 = __ldg(&g_col[e + 2]);
        int s3 = __ldg(&g_col[e + 3]);
        uint2 p0 = __ldg((const uint2*)(ybuf + (size_t)s0 * 64 + part * 4));
        uint2 p1 = __ldg((const uint2*)(ybuf + (size_t)s1 * 64 + part * 4));
        uint2 p2 = __ldg((const uint2*)(ybuf + (size_t)s2 * 64 + part * 4));
        uint2 p3 = __ldg((const uint2*)(ybuf + (size_t)s3 * 64 + part * 4));
        float2 f;
        f = __half22float2(*(__half2*)&p0.x); a0.x += f.x; a0.y += f.y;
        f = __half22float2(*(__half2*)&p0.y); a0.z += f.x; a0.w += f.y;
        f = __half22float2(*(__half2*)&p1.x); a1.x += f.x; a1.y += f.y;
        f = __half22float2(*(__half2*)&p1.y); a1.z += f.x; a1.w += f.y;
        f = __half22float2(*(__half2*)&p2.x); a2.x += f.x; a2.y += f.y;
        f = __half22float2(*(__half2*)&p2.y); a2.z += f.x; a2.w += f.y;
        f = __half22float2(*(__half2*)&p3.x); a3.x += f.x; a3.y += f.y;
        f = __half22float2(*(__half2*)&p3.y); a3.z += f.x; a3.w += f.y;
    }
    for (; e < end; e++) {
        int s0 = __ldg(&g_col[e]);
        uint2 p0 = __ldg((const uint2*)(ybuf + (size_t)s0 * 64 + part * 4));
        float2 f;
        f = __half22float2(*(__half2*)&p0.x); a0.x += f.x; a0.y += f.y;
        f = __half22float2(*(__half2*)&p0.y); a0.z += f.x; a0.w += f.y;
    }
    a0.x += a1.x + a2.x + a3.x;
    a0.y += a1.y + a2.y + a3.y;
    a0.z += a1.z + a2.z + a3.z;
    a0.w += a1.w + a2.w + a3.w;
    return a0;
}

// ---------------- fused: gather-1 + layer-2 transform + W2 matvec ----------------
#define HSTR 68
__global__ __launch_bounds__(128) void gather_gemm2_kernel(
    const float* __restrict__ W2, const float* __restrict__ b1)
{
    __shared__ float W2s[64 * 64];
    __shared__ float hs[8 * HSTR];

    const int tid  = threadIdx.x;
    const int ln   = tid >> 4;
    const int part = tid & 15;
    const int node = blockIdx.x * 8 + ln;

    for (int i = tid; i < 64 * 16; i += 128)
        ((float4*)W2s)[i] = ((const float4*)W2)[i];

    float4 h = make_float4(0.f, 0.f, 0.f, 0.f);
    if (node < N_NODES) {
        const int start = g_row_ptr[node];
        const int deg   = g_deg[N_NODES + node];
        float4 acc = gather_sum_h(g_yh, start, deg, part);
        float ri = g_rs_in[node];
        float ro = g_rs_out[node];
        float4 bb = ((const float4*)b1)[part];
        h.x = fmaxf(fmaf(acc.x, ri, bb.x), 0.f) * ro;
        h.y = fmaxf(fmaf(acc.y, ri, bb.y), 0.f) * ro;
        h.z = fmaxf(fmaf(acc.z, ri, bb.z), 0.f) * ro;
        h.w = fmaxf(fmaf(acc.w, ri, bb.w), 0.f) * ro;
    }
    float* hr = hs + ln * HSTR + part * 4;
    hr[0] = h.x; hr[1] = h.y; hr[2] = h.z; hr[3] = h.w;
    __syncthreads();

    float4 acc = make_float4(0.f, 0.f, 0.f, 0.f);
    const float* hrow = hs + ln * HSTR;
    const float4* W2s4 = (const float4*)W2s;
#pragma unroll 8
    for (int k = 0; k < 64; k++) {
        float hv = hrow[k];
        float4 w = W2s4[k * 16 + part];
        acc.x = fmaf(hv, w.x, acc.x);
        acc.y = fmaf(hv, w.y, acc.y);
        acc.z = fmaf(hv, w.z, acc.z);
        acc.w = fmaf(hv, w.w, acc.w);
    }
    if (node < N_NODES) {
        __half2 hp[2];
        hp[0] = __float22half2_rn(make_float2(acc.x, acc.y));
        hp[1] = __float22half2_rn(make_float2(acc.z, acc.w));
        *(uint2*)(g_y2h + (size_t)node * 64 + part * 4) = *(uint2*)&hp[0];
    }
}

// ---------------- final gather: out[n] = (sum g_y2h[src]) * rs_in + b2 (fp32) --------
__global__ __launch_bounds__(128) void gather_final_kernel(float4* __restrict__ outp,
                                                           const float* __restrict__ b2)
{
    const int tid  = threadIdx.x;
    const int node = blockIdx.x * 8 + (tid >> 4);
    const int part = tid & 15;
    if (node >= N_NODES) return;

    const int start = g_row_ptr[node];
    const int deg   = g_deg[N_NODES + node];
    float4 acc = gather_sum_h(g_y2h, start, deg, part);

    float ri = g_rs_in[node];
    float4 bb = ((const float4*)b2)[part];
    acc.x = fmaf(acc.x, ri, bb.x);
    acc.y = fmaf(acc.y, ri, bb.y);
    acc.z = fmaf(acc.z, ri, bb.z);
    acc.w = fmaf(acc.w, ri, bb.w);
    outp[(size_t)node * 16 + part] = acc;
}

// ---------------- launch ----------------
extern "C" void kernel_launch(void* const* d_in, const int* in_sizes, int n_in,
                              void* d_out, int out_size)
{
    // Positional defaults (setup_inputs dict order)
    const float* x   = (const float*)d_in[0];
    const int*   src = (const int*)d_in[1];
    const int*   dst = (const int*)d_in[2];
    const float* W1  = (const float*)d_in[3];
    const float* b1  = (const float*)d_in[4];
    const float* W2  = (const float*)d_in[5];
    const float* b2  = (const float*)d_in[6];
    int E = in_sizes[1];

    // Size-based identification (robust to metadata reordering)
    {
        int e_seen = 0, b_seen = 0;
        for (int i = 0; i < n_in; i++) {
            int s = in_sizes[i];
            if      (s == N_NODES * 128) x  = (const float*)d_in[i];
            else if (s == 128 * 64)      W1 = (const float*)d_in[i];
            else if (s == 64 * 64)       W2 = (const float*)d_in[i];
            else if (s == 64) { if (b_seen++ == 0) b1 = (const float*)d_in[i];
                                else               b2 = (const float*)d_in[i]; }
            else if (s > 64 * 64 && s != N_NODES * 128) {
                if (e_seen++ == 0) { src = (const int*)d_in[i]; E = s; }
                else                 dst = (const int*)d_in[i];
            }
        }
    }
    float* out = (float*)d_out;

    const int smem1 = (128 * 64 + 128 * 129) * (int)sizeof(float);  // 98816 B
    cudaFuncSetAttribute(gemm_kernel,
                         cudaFuncAttributeMaxDynamicSharedMemorySize, smem1);

    const int NB_E      = (E + 255) / 256;
    const int NB_GEMM   = (N_NODES + 127) / 128;
    const int NB_GATHER = (N_NODES + 7) / 8;

    // zero degrees via memset node (not a kernel launch)
    void* deg_ptr = nullptr;
    cudaGetSymbolAddress(&deg_ptr, g_deg);
    cudaMemsetAsync(deg_ptr, 0, 2 * N_NODES * sizeof(int), 0);

    degree_kernel<<<NB_E, 256>>>(src, dst, E);            // kernel launch 1
    scan_blocks_kernel<<<SCAN_BLOCKS, 256>>>();           // kernel launch 2
    scan_add_kernel<<<SCAN_BLOCKS, 256>>>();              // kernel launch 3 (+rsqrt)
    gemm_kernel<<<NB_GEMM, 128, smem1>>>(x, W1);          // kernel launch 4 <- ncu target
    csr_fill_kernel<<<NB_E, 256>>>(src, dst, E);          // kernel launch 5
    gather_gemm2_kernel<<<NB_GATHER, 128>>>(W2, b1);      // kernel launch 6
    gather_final_kernel<<<NB_GATHER, 128>>>((float4*)out, b2); // kernel launch 7
}

// round 14
// speedup vs baseline: 1.1377x; 1.0797x over previous
#include <cuda_runtime.h>
#include <cuda_fp16.h>
#include <math.h>

#define N_NODES 100000
#define E_MAX   1600000
#define SCAN_BLOCKS ((N_NODES + 255) / 256)   // 391

// ---------------- scratch (static __device__, no allocation) ----------------
__device__ int    g_deg[2 * N_NODES];   // [0..N): deg_out, [N..2N): deg_in (single memset)
__device__ float  g_rs_out[N_NODES];
__device__ float  g_rs_in[N_NODES];
__device__ __half g_yh[N_NODES * 64];   // layer-1 GEMM output, fp16 (gather-1 input)
__device__ __half g_y2h[N_NODES * 64];  // fused kernel output, fp16 (final-gather input)
__device__ int    g_row_ptr[N_NODES];   // CSR row starts (by dst)
__device__ int    g_cursor[N_NODES];    // fill cursors
__device__ int    g_col[E_MAX];         // CSR column indices (= src node)
__device__ int    g_partials[SCAN_BLOCKS];

// ---------------- f32x2 packed-FMA helpers (sm_103a) ----------------
__device__ __forceinline__ unsigned long long pack_dup(float a) {
    unsigned long long r;
    asm("mov.b64 %0, {%1, %1};" : "=l"(r) : "f"(a));
    return r;
}
__device__ __forceinline__ unsigned long long fma2(unsigned long long a,
                                                   unsigned long long b,
                                                   unsigned long long c) {
    unsigned long long d;
    asm("fma.rn.f32x2 %0, %1, %2, %3;" : "=l"(d) : "l"(a), "l"(b), "l"(c));
    return d;
}
__device__ __forceinline__ float2 unpack2(unsigned long long v) {
    float lo, hi;
    asm("mov.b64 {%0, %1}, %2;" : "=f"(lo), "=f"(hi) : "l"(v));
    return make_float2(lo, hi);
}

// ---------------- degrees ----------------
__global__ void degree_kernel(const int* __restrict__ src, const int* __restrict__ dst, int E) {
    int e = blockIdx.x * blockDim.x + threadIdx.x;
    if (e < E) {
        atomicAdd(&g_deg[src[e]], 1);             // deg_out
        atomicAdd(&g_deg[N_NODES + dst[e]], 1);   // deg_in
    }
}

// ---------------- CSR build ----------------
__global__ void scan_blocks_kernel() {
    __shared__ int sh[256];
    int t = threadIdx.x;
    int i = blockIdx.x * 256 + t;
    int v = (i < N_NODES) ? g_deg[N_NODES + i] : 0;
    sh[t] = v;
    __syncthreads();
#pragma unroll
    for (int off = 1; off < 256; off <<= 1) {
        int cur = sh[t];
        int add = (t >= off) ? sh[t - off] : 0;
        __syncthreads();
        sh[t] = cur + add;
        __syncthreads();
    }
    if (i < N_NODES) g_row_ptr[i] = sh[t] - v;      // block-local exclusive
    if (t == 255) g_partials[blockIdx.x] = sh[255]; // block total
}

// fused: partials-prefix (each block reduces partials[0..blk)) + finalize + rsqrt
__global__ void scan_add_kernel() {
    __shared__ int ssum[256];
    const int t = threadIdx.x;
    const int blk = blockIdx.x;
    int s = 0;
    for (int j = t; j < blk; j += 256) s += g_partials[j];   // <=2 iters (391 partials)
    ssum[t] = s;
    __syncthreads();
#pragma unroll
    for (int off = 128; off; off >>= 1) {
        if (t < off) ssum[t] += ssum[t + off];
        __syncthreads();
    }
    const int base = ssum[0];
    const int i = blk * 256 + t;
    if (i < N_NODES) {
        int r = g_row_ptr[i] + base;
        g_row_ptr[i] = r;
        g_cursor[i]  = r;
        g_rs_out[i] = rsqrtf((float)max(g_deg[i], 1));
        g_rs_in[i]  = rsqrtf((float)max(g_deg[N_NODES + i], 1));
    }
}

__global__ void csr_fill_kernel(const int* __restrict__ src, const int* __restrict__ dst, int E) {
    int e = blockIdx.x * blockDim.x + threadIdx.x;
    if (e < E) {
        int d = dst[e];
        int pos = atomicAdd(&g_cursor[d], 1);
        g_col[pos] = src[e];
    }
}

// ---------------- GEMM1: g_yh[n,64] = fp16( ro[n] * (x[n,:] @ W1) )   (K=128) --------
// 128 threads, 128 nodes/block. Thread (tq=tid>>2, tc4=(tid&3)*4) computes
// nodes {tq+32i} x 16 cols. Row-scale folded into epilogue so x needs NO smem
// staging (direct LDG.128, L1-resident tile). W in 32KB static smem; its
// LDS.128 register quads are consumed directly as f32x2 pairs. Inner loop uses
// packed fma.rn.f32x2 -> 32 FFMA2 + 4 packs + 4 LDS.128 per k.
__global__ __launch_bounds__(128, 4) void gemm_kernel(
    const float* __restrict__ X, const float* __restrict__ W)
{
    __shared__ __align__(16) float Ws[128 * 64];
    const int tid = threadIdx.x;
    const int node0 = blockIdx.x * 128;

    for (int i = tid; i < 128 * 16; i += 128)
        ((float4*)Ws)[i] = ((const float4*)W)[i];
    __syncthreads();

    const int tq  = tid >> 2;          // 0..31
    const int tc4 = (tid & 3) * 4;     // float4-index base into W row (cols tc4*4..+15)

    int nidx[4];
#pragma unroll
    for (int i = 0; i < 4; i++) {
        int n = node0 + tq + 32 * i;
        nidx[i] = (n < N_NODES) ? n : (N_NODES - 1);   // clamp OOB loads (stores guarded)
    }

    unsigned long long acc[4][8];
#pragma unroll
    for (int i = 0; i < 4; i++)
#pragma unroll
        for (int j = 0; j < 8; j++) acc[i][j] = 0ull;  // {+0.f,+0.f}

    const ulonglong2* Wsu = (const ulonglong2*)Ws;     // index == float4 index
#pragma unroll 2
    for (int k4 = 0; k4 < 32; k4++) {
        float4 xv[4];
#pragma unroll
        for (int i = 0; i < 4; i++)
            xv[i] = __ldg((const float4*)(X + (size_t)nidx[i] * 128) + k4);
#pragma unroll
        for (int kk = 0; kk < 4; kk++) {
            const int k = k4 * 4 + kk;
            ulonglong2 w[4];
#pragma unroll
            for (int j = 0; j < 4; j++)
                w[j] = Wsu[k * 16 + tc4 + j];
#pragma unroll
            for (int i = 0; i < 4; i++) {
                unsigned long long xp = pack_dup(((const float*)&xv[i])[kk]);
#pragma unroll
                for (int j = 0; j < 4; j++) {
                    acc[i][j * 2]     = fma2(xp, w[j].x, acc[i][j * 2]);
                    acc[i][j * 2 + 1] = fma2(xp, w[j].y, acc[i][j * 2 + 1]);
                }
            }
        }
    }

    // epilogue: scale by rs_out, convert fp16, store 16 cols = 2 x uint4
#pragma unroll
    for (int i = 0; i < 4; i++) {
        int node = node0 + tq + 32 * i;
        if (node < N_NODES) {
            float ro = g_rs_out[node];
            __half2 hp[8];
#pragma unroll
            for (int j = 0; j < 8; j++) {
                float2 f = unpack2(acc[i][j]);
                hp[j] = __float22half2_rn(make_float2(f.x * ro, f.y * ro));
            }
            uint4* dstp = (uint4*)(g_yh + (size_t)node * 64 + tc4 * 4);
            dstp[0] = *(uint4*)&hp[0];
            dstp[1] = *(uint4*)&hp[4];
        }
    }
}

// ---------------- 4-way unrolled CSR gather sum over fp16 rows ----------------
// part in 0..15 covers 4 cols; per edge loads uint2 (4 halves = 8B).
__device__ __forceinline__ float4 gather_sum_h(const __half* __restrict__ ybuf,
                                               int start, int deg, int part)
{
    float4 a0 = make_float4(0.f, 0.f, 0.f, 0.f);
    float4 a1 = make_float4(0.f, 0.f, 0.f, 0.f);
    float4 a2 = make_float4(0.f, 0.f, 0.f, 0.f);
    float4 a3 = make_float4(0.f, 0.f, 0.f, 0.f);
    const int end = start + deg;
    int e = start;
    for (; e + 3 < end; e += 4) {
        int s0 = __ldg(&g_col[e]);
        int s1 = __ldg(&g_col[e + 1]);
        int s2 = __ldg(&g_col[e + 2]);
        int s3 = __ldg(&g_col[e + 3]);
        uint2 p0 = __ldg((const uint2*)(ybuf + (size_t)s0 * 64 + part * 4));
        uint2 p1 = __ldg((const uint2*)(ybuf + (size_t)s1 * 64 + part * 4));
        uint2 p2 = __ldg((const uint2*)(ybuf + (size_t)s2 * 64 + part * 4));
        uint2 p3 = __ldg((const uint2*)(ybuf + (size_t)s3 * 64 + part * 4));
        float2 f;
        f = __half22float2(*(__half2*)&p0.x); a0.x += f.x; a0.y += f.y;
        f = __half22float2(*(__half2*)&p0.y); a0.z += f.x; a0.w += f.y;
        f = __half22float2(*(__half2*)&p1.x); a1.x += f.x; a1.y += f.y;
        f = __half22float2(*(__half2*)&p1.y); a1.z += f.x; a1.w += f.y;
        f = __half22float2(*(__half2*)&p2.x); a2.x += f.x; a2.y += f.y;
        f = __half22float2(*(__half2*)&p2.y); a2.z += f.x; a2.w += f.y;
        f = __half22float2(*(__half2*)&p3.x); a3.x += f.x; a3.y += f.y;
        f = __half22float2(*(__half2*)&p3.y); a3.z += f.x; a3.w += f.y;
    }
    for (; e < end; e++) {
        int s0 = __ldg(&g_col[e]);
        uint2 p0 = __ldg((const uint2*)(ybuf + (size_t)s0 * 64 + part * 4));
        float2 f;
        f = __half22float2(*(__half2*)&p0.x); a0.x += f.x; a0.y += f.y;
        f = __half22float2(*(__half2*)&p0.y); a0.z += f.x; a0.w += f.y;
    }
    a0.x += a1.x + a2.x + a3.x;
    a0.y += a1.y + a2.y + a3.y;
    a0.z += a1.z + a2.z + a3.z;
    a0.w += a1.w + a2.w + a3.w;
    return a0;
}

// ---------------- fused: gather-1 + layer-2 transform + W2 matvec ----------------
#define HSTR 68
__global__ __launch_bounds__(128) void gather_gemm2_kernel(
    const float* __restrict__ W2, const float* __restrict__ b1)
{
    __shared__ float W2s[64 * 64];
    __shared__ float hs[8 * HSTR];

    const int tid  = threadIdx.x;
    const int ln   = tid >> 4;
    const int part = tid & 15;
    const int node = blockIdx.x * 8 + ln;

    for (int i = tid; i < 64 * 16; i += 128)
        ((float4*)W2s)[i] = ((const float4*)W2)[i];

    float4 h = make_float4(0.f, 0.f, 0.f, 0.f);
    if (node < N_NODES) {
        const int start = g_row_ptr[node];
        const int deg   = g_deg[N_NODES + node];
        float4 acc = gather_sum_h(g_yh, start, deg, part);
        float ri = g_rs_in[node];
        float ro = g_rs_out[node];
        float4 bb = ((const float4*)b1)[part];
        h.x = fmaxf(fmaf(acc.x, ri, bb.x), 0.f) * ro;
        h.y = fmaxf(fmaf(acc.y, ri, bb.y), 0.f) * ro;
        h.z = fmaxf(fmaf(acc.z, ri, bb.z), 0.f) * ro;
        h.w = fmaxf(fmaf(acc.w, ri, bb.w), 0.f) * ro;
    }
    float* hr = hs + ln * HSTR + part * 4;
    hr[0] = h.x; hr[1] = h.y; hr[2] = h.z; hr[3] = h.w;
    __syncthreads();

    float4 acc = make_float4(0.f, 0.f, 0.f, 0.f);
    const float* hrow = hs + ln * HSTR;
    const float4* W2s4 = (const float4*)W2s;
#pragma unroll 8
    for (int k = 0; k < 64; k++) {
        float hv = hrow[k];
        float4 w = W2s4[k * 16 + part];
        acc.x = fmaf(hv, w.x, acc.x);
        acc.y = fmaf(hv, w.y, acc.y);
        acc.z = fmaf(hv, w.z, acc.z);
        acc.w = fmaf(hv, w.w, acc.w);
    }
    if (node < N_NODES) {
        __half2 hp[2];
        hp[0] = __float22half2_rn(make_float2(acc.x, acc.y));
        hp[1] = __float22half2_rn(make_float2(acc.z, acc.w));
        *(uint2*)(g_y2h + (size_t)node * 64 + part * 4) = *(uint2*)&hp[0];
    }
}

// ---------------- final gather: out[n] = (sum g_y2h[src]) * rs_in + b2 (fp32) --------
__global__ __launch_bounds__(128) void gather_final_kernel(float4* __restrict__ outp,
                                                           const float* __restrict__ b2)
{
    const int tid  = threadIdx.x;
    const int node = blockIdx.x * 8 + (tid >> 4);
    const int part = tid & 15;
    if (node >= N_NODES) return;

    const int start = g_row_ptr[node];
    const int deg   = g_deg[N_NODES + node];
    float4 acc = gather_sum_h(g_y2h, start, deg, part);

    float ri = g_rs_in[node];
    float4 bb = ((const float4*)b2)[part];
    acc.x = fmaf(acc.x, ri, bb.x);
    acc.y = fmaf(acc.y, ri, bb.y);
    acc.z = fmaf(acc.z, ri, bb.z);
    acc.w = fmaf(acc.w, ri, bb.w);
    outp[(size_t)node * 16 + part] = acc;
}

// ---------------- launch ----------------
extern "C" void kernel_launch(void* const* d_in, const int* in_sizes, int n_in,
                              void* d_out, int out_size)
{
    // Positional defaults (setup_inputs dict order)
    const float* x   = (const float*)d_in[0];
    const int*   src = (const int*)d_in[1];
    const int*   dst = (const int*)d_in[2];
    const float* W1  = (const float*)d_in[3];
    const float* b1  = (const float*)d_in[4];
    const float* W2  = (const float*)d_in[5];
    const float* b2  = (const float*)d_in[6];
    int E = in_sizes[1];

    // Size-based identification (robust to metadata reordering)
    {
        int e_seen = 0, b_seen = 0;
        for (int i = 0; i < n_in; i++) {
            int s = in_sizes[i];
            if      (s == N_NODES * 128) x  = (const float*)d_in[i];
            else if (s == 128 * 64)      W1 = (const float*)d_in[i];
            else if (s == 64 * 64)       W2 = (const float*)d_in[i];
            else if (s == 64) { if (b_seen++ == 0) b1 = (const float*)d_in[i];
                                else               b2 = (const float*)d_in[i]; }
            else if (s > 64 * 64 && s != N_NODES * 128) {
                if (e_seen++ == 0) { src = (const int*)d_in[i]; E = s; }
                else                 dst = (const int*)d_in[i];
            }
        }
    }
    float* out = (float*)d_out;

    const int NB_E      = (E + 255) / 256;
    const int NB_GEMM   = (N_NODES + 127) / 128;
    const int NB_GATHER = (N_NODES + 7) / 8;

    // zero degrees via memset node (not a kernel launch)
    void* deg_ptr = nullptr;
    cudaGetSymbolAddress(&deg_ptr, g_deg);
    cudaMemsetAsync(deg_ptr, 0, 2 * N_NODES * sizeof(int), 0);

    degree_kernel<<<NB_E, 256>>>(src, dst, E);            // kernel launch 1
    scan_blocks_kernel<<<SCAN_BLOCKS, 256>>>();           // kernel launch 2
    scan_add_kernel<<<SCAN_BLOCKS, 256>>>();              // kernel launch 3 (+rsqrt)
    gemm_kernel<<<NB_GEMM, 128>>>(x, W1);                 // kernel launch 4 <- ncu target
    csr_fill_kernel<<<NB_E, 256>>>(src, dst, E);          // kernel launch 5
    gather_gemm2_kernel<<<NB_GATHER, 128>>>(W2, b1);      // kernel launch 6
    gather_final_kernel<<<NB_GATHER, 128>>>((float4*)out, b2); // kernel launch 7
}